// round 1
// baseline (speedup 1.0000x reference)
#include <cuda_runtime.h>
#include <cstddef>

#define T_STEPS 8192
#define NRES    2048
#define DIN     64
#define DOUT    64
#define GBLK    128
#define ROWS_PER_CTA 16
#define TPB     256
#define LEAK    0.3f
#define NOISE_L 0.01f

// ---------------- scratch (device globals: allocation-free) ----------------
__device__ float    g_drive [T_STEPS * NRES];   // 64 MB
__device__ float    g_states[T_STEPS * NRES];   // 64 MB
__device__ float    g_sbuf  [2][NRES];          // double-buffered reservoir state
__device__ unsigned g_bar_count;
__device__ volatile unsigned g_bar_gen;

// ---------------- grid-wide barrier (all GBLK CTAs co-resident) -------------
__device__ __forceinline__ void grid_barrier() {
    __syncthreads();
    if (threadIdx.x == 0) {
        unsigned gen = g_bar_gen;
        __threadfence();                      // publish this CTA's stores
        unsigned prev = atomicAdd(&g_bar_count, 1u);
        if (prev == GBLK - 1u) {
            g_bar_count = 0u;
            __threadfence();
            g_bar_gen = gen + 1u;             // release
        } else {
            while (g_bar_gen == gen) { }      // spin on L2 (volatile)
            __threadfence();                  // acquire
        }
    }
    __syncthreads();
}

// ---------------- kernel 1: drive = u @ W_in^T + 0.01*noise -----------------
// grid: (NRES/256, T/32); block computes 32 timesteps x 256 reservoir units
__global__ void drive_kernel(const float* __restrict__ u,
                             const float* __restrict__ noise,
                             const float* __restrict__ W_in) {
    __shared__ float4 u_sh[32 * (DIN / 4)];   // 32 t x 64 floats = 8 KB
    const int n  = blockIdx.x * 256 + threadIdx.x;
    const int t0 = blockIdx.y * 32;

    float4 w[DIN / 4];
    const float4* Wv = reinterpret_cast<const float4*>(W_in);
    #pragma unroll
    for (int j = 0; j < DIN / 4; j++) w[j] = Wv[(size_t)n * (DIN / 4) + j];

    const float4* uv = reinterpret_cast<const float4*>(u + (size_t)t0 * DIN);
    for (int i = threadIdx.x; i < 32 * (DIN / 4); i += 256) u_sh[i] = uv[i];
    __syncthreads();

    for (int t = 0; t < 32; t++) {
        float acc = 0.f;
        #pragma unroll
        for (int j = 0; j < DIN / 4; j++) {
            float4 uu = u_sh[t * (DIN / 4) + j];
            acc += w[j].x * uu.x + w[j].y * uu.y + w[j].z * uu.z + w[j].w * uu.w;
        }
        size_t idx = (size_t)(t0 + t) * NRES + n;
        g_drive[idx] = acc + NOISE_L * noise[idx];
    }
}

// ---------------- kernel 2: persistent reservoir recurrence -----------------
// 128 CTAs x 256 thr; CTA owns 16 rows of W; warp owns 2 rows; lane owns 64
// columns (float4 chunks at index lane + 32*j). W lives in registers.
__global__ void __launch_bounds__(TPB) reservoir_kernel(const float* __restrict__ W) {
    __shared__ float4 s_sh[NRES / 4];         // full state, 8 KB

    const int cta  = blockIdx.x;
    const int tid  = threadIdx.x;
    const int warp = tid >> 5;
    const int lane = tid & 31;
    const int r0   = cta * ROWS_PER_CTA + warp * 2;
    const int r1   = r0 + 1;

    // Load this thread's W slice into registers (one-time, coalesced)
    const float4* Wv = reinterpret_cast<const float4*>(W);
    float4 w0[16], w1[16];
    #pragma unroll
    for (int j = 0; j < 16; j++) {
        w0[j] = Wv[(size_t)r0 * (NRES / 4) + lane + 32 * j];
        w1[j] = Wv[(size_t)r1 * (NRES / 4) + lane + 32 * j];
    }

    // s(0) = 0
    if (tid < ROWS_PER_CTA) g_sbuf[0][cta * ROWS_PER_CTA + tid] = 0.f;
    float sp0 = 0.f, sp1 = 0.f;                // previous state of owned rows
    grid_barrier();

    #pragma unroll 1
    for (int t = 0; t < T_STEPS; t++) {
        // prefetch input drive early (DRAM latency overlaps with s staging)
        float d0 = 0.f, d1 = 0.f;
        if (lane == 0) {
            d0 = g_drive[(size_t)t * NRES + r0];
            d1 = g_drive[(size_t)t * NRES + r1];
        }

        // stage current state into SMEM; MUST bypass L1 (written by other SMs)
        const float4* sin = reinterpret_cast<const float4*>(g_sbuf[t & 1]);
        for (int i = tid; i < NRES / 4; i += TPB) s_sh[i] = __ldcg(&sin[i]);
        __syncthreads();

        // two independent accumulator chains per row to shorten FFMA dep chain
        float a0 = 0.f, a0b = 0.f, a1 = 0.f, a1b = 0.f;
        #pragma unroll
        for (int j = 0; j < 16; j += 2) {
            float4 sv  = s_sh[lane + 32 * j];
            float4 sv2 = s_sh[lane + 32 * (j + 1)];
            a0  += w0[j].x * sv.x  + w0[j].y * sv.y  + w0[j].z * sv.z  + w0[j].w * sv.w;
            a1  += w1[j].x * sv.x  + w1[j].y * sv.y  + w1[j].z * sv.z  + w1[j].w * sv.w;
            a0b += w0[j+1].x * sv2.x + w0[j+1].y * sv2.y + w0[j+1].z * sv2.z + w0[j+1].w * sv2.w;
            a1b += w1[j+1].x * sv2.x + w1[j+1].y * sv2.y + w1[j+1].z * sv2.z + w1[j+1].w * sv2.w;
        }
        float acc0 = a0 + a0b;
        float acc1 = a1 + a1b;
        #pragma unroll
        for (int off = 16; off > 0; off >>= 1) {
            acc0 += __shfl_xor_sync(0xffffffffu, acc0, off);
            acc1 += __shfl_xor_sync(0xffffffffu, acc1, off);
        }

        if (lane == 0) {
            float ns0 = (1.f - LEAK) * sp0 + LEAK * tanhf(d0 + acc0);
            float ns1 = (1.f - LEAK) * sp1 + LEAK * tanhf(d1 + acc1);
            sp0 = ns0; sp1 = ns1;
            float* so = g_sbuf[(t + 1) & 1];
            so[r0] = ns0;
            so[r1] = ns1;
            g_states[(size_t)t * NRES + r0] = ns0;
            g_states[(size_t)t * NRES + r1] = ns1;
        }
        grid_barrier();                        // publishes stores, syncs grid
    }
}

// ---------------- kernel 3: out = states @ w_out^T + b_out ------------------
// grid: T/64 blocks; block computes 64 t-rows x all 64 outputs
__global__ void proj_kernel(const float* __restrict__ w_out,
                            const float* __restrict__ b_out,
                            float* __restrict__ out) {
    __shared__ float s_sh[64][33];
    __shared__ float w_sh[DOUT][33];
    const int t0  = blockIdx.x * 64;
    const int tid = threadIdx.x;
    const int tx  = tid & 15;                 // output group
    const int ty  = tid >> 4;                 // t-row group
    float acc[4][4] = {};

    for (int kc = 0; kc < NRES; kc += 32) {
        for (int i = tid; i < 64 * 32; i += 256) {
            int r = i >> 5, k = i & 31;
            s_sh[r][k] = g_states[(size_t)(t0 + r) * NRES + kc + k];
        }
        for (int i = tid; i < DOUT * 32; i += 256) {
            int o = i >> 5, k = i & 31;
            w_sh[o][k] = w_out[(size_t)o * NRES + kc + k];
        }
        __syncthreads();
        for (int k = 0; k < 32; k++) {
            float sv[4], wv[4];
            #pragma unroll
            for (int i = 0; i < 4; i++) sv[i] = s_sh[ty * 4 + i][k];
            #pragma unroll
            for (int j = 0; j < 4; j++) wv[j] = w_sh[tx * 4 + j][k];
            #pragma unroll
            for (int i = 0; i < 4; i++)
                #pragma unroll
                for (int j = 0; j < 4; j++)
                    acc[i][j] += sv[i] * wv[j];
        }
        __syncthreads();
    }
    #pragma unroll
    for (int i = 0; i < 4; i++)
        #pragma unroll
        for (int j = 0; j < 4; j++)
            out[(size_t)(t0 + ty * 4 + i) * DOUT + tx * 4 + j] = acc[i][j] + b_out[tx * 4 + j];
}

// ---------------- launch --------------------------------------------------
extern "C" void kernel_launch(void* const* d_in, const int* in_sizes, int n_in,
                              void* d_out, int out_size) {
    const float* u     = (const float*)d_in[0];  // (8192, 64)
    const float* noise = (const float*)d_in[1];  // (8192, 2048)
    const float* W_in  = (const float*)d_in[2];  // (2048, 64)
    const float* W     = (const float*)d_in[3];  // (2048, 2048)
    const float* w_out = (const float*)d_in[4];  // (64, 2048)
    const float* b_out = (const float*)d_in[5];  // (64,)
    float* out = (float*)d_out;                  // (8192, 64)

    drive_kernel<<<dim3(NRES / 256, T_STEPS / 32), 256>>>(u, noise, W_in);
    reservoir_kernel<<<GBLK, TPB>>>(W);
    proj_kernel<<<T_STEPS / 64, 256>>>(w_out, b_out, out);
}